// round 3
// baseline (speedup 1.0000x reference)
#include <cuda_runtime.h>
#include <cuda_bf16.h>
#include <math.h>

typedef unsigned long long ull;

// ---------------- problem constants ----------------
#define NB       64
#define NNODES   1296        // 16*81
#define NC       43
#define OD       16
#define CO_TIMES_OD 688      // 43*16
#define CO4      172         // 688/4

// packed f32x2 FMA (Blackwell sm_103a): two fp32 MACs per instruction, bit-exact fp32
#define FMA2(a,x,y) asm("fma.rn.f32x2 %0, %1, %2, %0;" : "+l"(a) : "l"(x), "l"(y))

static __device__ __forceinline__ float f2lo(ull v){ return __uint_as_float((unsigned)v); }
static __device__ __forceinline__ float f2hi(ull v){ return __uint_as_float((unsigned)(v>>32)); }

// ---------------- device scratch ----------------
__device__ float2 g_w1p[69120];                    // conv1 weights dup'd: [(ci*9+ky)][co][kx pad 10]
__device__ float2 g_w2p[2097152];                  // prim  weights dup'd: [(ci*8+ky)][co][kx 8]
__device__ float  g_h[NB * 256 * 24 * 24];         // conv1 output (relu'd)
__device__ float  g_u[NB * NNODES * 8];            // primary capsules (squashed in place)
__device__ ull    g_pri[(size_t)NB * NNODES * CO4];// priors, bf16x4 packed (114MB)
__device__ float  g_logits[NB * NNODES * NC];
__device__ float  g_s[NB * CO_TIMES_OD];
__device__ float  g_caps[NB * CO_TIMES_OD];

static __device__ __forceinline__ float4 unpk(ull v) {
    return make_float4(
        __bfloat162float(__ushort_as_bfloat16((unsigned short)(v))),
        __bfloat162float(__ushort_as_bfloat16((unsigned short)(v >> 16))),
        __bfloat162float(__ushort_as_bfloat16((unsigned short)(v >> 32))),
        __bfloat162float(__ushort_as_bfloat16((unsigned short)(v >> 48))));
}

// ---------------- weight dup/transpose ----------------
__global__ void k_tr1p(const float* __restrict__ w) {
    int idx = blockIdx.x * 256 + threadIdx.x;
    if (idx >= 69120) return;
    int kx = idx % 10; int t = idx / 10;
    int co = t & 255;  int cik = t >> 8;    // 0..26
    int ci = cik / 9, ky = cik - ci * 9;
    float v = (kx < 9) ? w[co * 243 + ci * 81 + ky * 9 + kx] : 0.f;
    g_w1p[idx] = make_float2(v, v);
}
__global__ void k_tr2p(const float* __restrict__ w) {
    int idx = blockIdx.x * 256 + threadIdx.x;   // 2,097,152 exact
    int kx = idx & 7; int co = (idx >> 3) & 127; int t = idx >> 10;
    int ky = t & 7;  int ci = t >> 3;
    float v = w[co * 16384 + ci * 64 + ky * 8 + kx];
    g_w2p[idx] = make_float2(v, v);
}

// ---------------- conv1: batch-paired f32x2, (64,3,32,32) -> (64,256,24,24) ----------------
__global__ __launch_bounds__(256, 2) void k_conv1(const float* __restrict__ x,
                                                  const float* __restrict__ bias) {
    int oy = blockIdx.x, bp = blockIdx.y;
    int b0 = bp, b1 = bp + 32;
    int co = threadIdx.x;
    __shared__ float2 xs[864];           // [3 ci][9 r][32 col], pair (b0,b1)
    for (int idx = co; idx < 864; idx += 256) {
        int ci = idx / 288, rem = idx - ci * 288;
        int r = rem >> 5, col = rem & 31;
        int off = (ci * 32 + oy + r) * 32 + col;
        xs[idx] = make_float2(x[b0 * 3072 + off], x[b1 * 3072 + off]);
    }
    __syncthreads();
    const ull* xsu = (const ull*)xs;
    float bv = bias[co];
#pragma unroll 1
    for (int h = 0; h < 2; h++) {        // two halves of the 24-wide output row
        ull acc[12];
#pragma unroll
        for (int i = 0; i < 12; i++) acc[i] = 0ull;
        for (int ci = 0; ci < 3; ci++) {
#pragma unroll
            for (int ky = 0; ky < 9; ky++) {
                ull in[20];
                const ulonglong2* ip = (const ulonglong2*)(xsu + ci * 288 + ky * 32 + h * 12);
#pragma unroll
                for (int j = 0; j < 10; j++) { ulonglong2 t = ip[j]; in[2*j] = t.x; in[2*j+1] = t.y; }
                ull w[10];
                const ulonglong2* wp = (const ulonglong2*)(g_w1p + ((ci * 9 + ky) * 256 + co) * 10);
#pragma unroll
                for (int j = 0; j < 5; j++) { ulonglong2 t = wp[j]; w[2*j] = t.x; w[2*j+1] = t.y; }
#pragma unroll
                for (int kx = 0; kx < 9; kx++)
#pragma unroll
                    for (int ox = 0; ox < 12; ox++)
                        FMA2(acc[ox], in[ox + kx], w[kx]);
            }
        }
        float* h0 = &g_h[((b0 * 256 + co) * 24 + oy) * 24 + h * 12];
        float* h1 = &g_h[((b1 * 256 + co) * 24 + oy) * 24 + h * 12];
#pragma unroll
        for (int ox = 0; ox < 12; ox++) {
            h0[ox] = fmaxf(f2lo(acc[ox]) + bv, 0.f);
            h1[ox] = fmaxf(f2hi(acc[ox]) + bv, 0.f);
        }
    }
}

// ---------------- prim conv: batch-paired f32x2, 8x8 s2 -> caps layout ----------------
__global__ __launch_bounds__(256, 2) void k_prim(const float* __restrict__ bias) {
    int oy = blockIdx.x, bp = blockIdx.y;
    int b0 = bp, b1 = bp + 32;
    int tid = threadIdx.x;
    int kh = tid >> 7;          // K-range half
    int co = tid & 127;
    __shared__ float2 hs[6144];   // 48KB: [32 ci][8 r][24 col], pair (b0,b1)
    const ull* hsu = (const ull*)hs;
    ull acc[9];
#pragma unroll
    for (int i = 0; i < 9; i++) acc[i] = 0ull;

    for (int cc = 0; cc < 8; cc++) {      // 8 chunks of 32 input channels
        __syncthreads();
        for (int idx = tid; idx < 6144; idx += 256) {
            int ci = idx / 192, rem = idx - ci * 192;
            int r = rem / 24, col = rem - r * 24;
            int off = ((cc * 32 + ci) * 24 + 2 * oy + r) * 24 + col;
            hs[idx] = make_float2(g_h[b0 * 147456 + off], g_h[b1 * 147456 + off]);
        }
        __syncthreads();
        for (int cil = kh * 16; cil < kh * 16 + 16; cil++) {
            int g = cc * 32 + cil;
#pragma unroll
            for (int ky = 0; ky < 8; ky++) {
                ull in[24];
                const ulonglong2* ip = (const ulonglong2*)(hsu + cil * 192 + ky * 24);
#pragma unroll
                for (int j = 0; j < 12; j++) { ulonglong2 t = ip[j]; in[2*j] = t.x; in[2*j+1] = t.y; }
                ull w[8];
                const ulonglong2* wp = (const ulonglong2*)(g_w2p + ((g * 8 + ky) * 128 + co) * 8);
#pragma unroll
                for (int j = 0; j < 4; j++) { ulonglong2 t = wp[j]; w[2*j] = t.x; w[2*j+1] = t.y; }
#pragma unroll
                for (int kx = 0; kx < 8; kx++)
#pragma unroll
                    for (int ox = 0; ox < 9; ox++)
                        FMA2(acc[ox], in[2 * ox + kx], w[kx]);
            }
        }
    }
    __syncthreads();
    ull* cm = (ull*)hs;
    if (kh == 1) {
#pragma unroll
        for (int ox = 0; ox < 9; ox++) cm[co * 9 + ox] = acc[ox];
    }
    __syncthreads();
    if (kh == 0) {
        float bv = bias[co];
        int i = co >> 4, g2 = co & 15;
#pragma unroll
        for (int ox = 0; ox < 9; ox++) {
            ull o = cm[co * 9 + ox];
            float v0 = f2lo(acc[ox]) + f2lo(o) + bv;
            float v1 = f2hi(acc[ox]) + f2hi(o) + bv;
            int n = g2 * 81 + oy * 9 + ox;
            g_u[(b0 * NNODES + n) * 8 + i] = v0;
            g_u[(b1 * NNODES + n) * 8 + i] = v1;
        }
    }
}

// ---------------- squash primary capsules (dim 8, in place) ----------------
__global__ void k_squash_u() {
    int node = blockIdx.x * 256 + threadIdx.x;
    if (node >= NB * NNODES) return;
    float v[8]; float sn = 0.f;
#pragma unroll
    for (int i = 0; i < 8; i++) { v[i] = g_u[node * 8 + i]; sn = fmaf(v[i], v[i], sn); }
    float f = sqrtf(sn) / (1.f + sn);
#pragma unroll
    for (int i = 0; i < 8; i++) g_u[node * 8 + i] = v[i] * f;
}

// ---------------- priors[b,n,c,o] = sum_i u[b,n,i] * W[n,c,i,o]; store bf16x4 ----------------
__global__ __launch_bounds__(256) void k_priors(const float* __restrict__ route_w) {
    int n = blockIdx.x, tid = threadIdx.x;
    __shared__ float rw[NC * 8 * OD];   // 5504
    __shared__ float us[NB * 8];        // 512
    for (int idx = tid; idx < 5504; idx += 256) rw[idx] = route_w[n * 5504 + idx];
    for (int idx = tid; idx < 512; idx += 256) {
        int b = idx >> 3, i = idx & 7;
        us[idx] = g_u[(b * NNODES + n) * 8 + i];
    }
    __syncthreads();
    if (tid < CO4) {
        int c = tid >> 2;
        int obase = (tid & 3) * 4;
        const float* rwc = &rw[c * 128 + obase];
        for (int b = 0; b < NB; b++) {
            const float* ub = &us[b * 8];
            float4 sum = make_float4(0.f, 0.f, 0.f, 0.f);
#pragma unroll
            for (int i = 0; i < 8; i++) {
                float u = ub[i];
                sum.x = fmaf(u, rwc[i * 16 + 0], sum.x);
                sum.y = fmaf(u, rwc[i * 16 + 1], sum.y);
                sum.z = fmaf(u, rwc[i * 16 + 2], sum.z);
                sum.w = fmaf(u, rwc[i * 16 + 3], sum.w);
            }
            ull v = (ull)__bfloat16_as_ushort(__float2bfloat16(sum.x))
                  | ((ull)__bfloat16_as_ushort(__float2bfloat16(sum.y)) << 16)
                  | ((ull)__bfloat16_as_ushort(__float2bfloat16(sum.z)) << 32)
                  | ((ull)__bfloat16_as_ushort(__float2bfloat16(sum.w)) << 48);
            g_pri[(size_t)(b * NNODES + n) * CO4 + tid] = v;
        }
    }
}

// ---------------- zero helpers ----------------
__global__ void k_zero_s() {
    int i = blockIdx.x * 256 + threadIdx.x;
    if (i < NB * CO_TIMES_OD) g_s[i] = 0.f;
}
__global__ void k_zero_logits() {
    int i = blockIdx.x * 256 + threadIdx.x;
    if (i < NB * NNODES * NC) g_logits[i] = 0.f;
}

// ---------------- iter0: s[b] = sum_n priors (uniform probs folded into squash scale) ----------------
__global__ void k_reduce0() {
    int b = blockIdx.x, tid = threadIdx.x;
    if (tid >= CO4) return;
    const ull* p = &g_pri[(size_t)b * NNODES * CO4 + tid];
    float4 acc = make_float4(0.f, 0.f, 0.f, 0.f);
    for (int n = 0; n < NNODES; n++) {
        float4 q = unpk(p[(size_t)n * CO4]);
        acc.x += q.x; acc.y += q.y; acc.z += q.z; acc.w += q.w;
    }
    float* sp = &g_s[b * CO_TIMES_OD + tid * 4];
    sp[0] = acc.x; sp[1] = acc.y; sp[2] = acc.z; sp[3] = acc.w;
}

// ---------------- squash s -> output capsules ----------------
__global__ void k_squash_out(float scale) {
    int idx = blockIdx.x * 256 + threadIdx.x;
    if (idx >= NB * NC) return;
    float v[16]; float sn = 0.f;
#pragma unroll
    for (int o = 0; o < 16; o++) { v[o] = g_s[idx * 16 + o] * scale; sn = fmaf(v[o], v[o], sn); }
    float f = sqrtf(sn) / (1.f + sn);
#pragma unroll
    for (int o = 0; o < 16; o++) g_caps[idx * 16 + o] = v[o] * f;
}

// ---------------- routing iteration: delta -> logits -> softmax -> s accumulate ----------------
__global__ __launch_bounds__(256) void k_iter() {
    int b = blockIdx.y, n0 = blockIdx.x * 16, tid = threadIdx.x;
    __shared__ float dsum[48];
    __shared__ float probs[64];
    if (tid >= 43 && tid < 64) probs[tid] = 0.f;

    const float4* caps4 = reinterpret_cast<const float4*>(g_caps);
    float4 outs = make_float4(0.f, 0.f, 0.f, 0.f);
    if (tid < CO4) outs = caps4[b * CO4 + tid];
    float4 acc = make_float4(0.f, 0.f, 0.f, 0.f);

    for (int nn = 0; nn < 16; nn++) {
        int n = n0 + nn;
        float4 pr = make_float4(0.f, 0.f, 0.f, 0.f);
        if (tid < CO4) pr = unpk(g_pri[(size_t)(b * NNODES + n) * CO4 + tid]);
        // delta_c = sum_o priors * outputs  (4 lanes per class, reduce width 4)
        float t = pr.x * outs.x + pr.y * outs.y + pr.z * outs.z + pr.w * outs.w;
        t += __shfl_xor_sync(0xffffffffu, t, 2, 4);
        t += __shfl_xor_sync(0xffffffffu, t, 1, 4);
        if (tid < CO4 && (tid & 3) == 0) dsum[tid >> 2] = t;
        __syncthreads();
        if (tid < 32) {
            int c1 = tid, c2 = tid + 32;
            int L = (b * NNODES + n) * NC;
            float l1 = (c1 < NC) ? g_logits[L + c1] + dsum[c1] : -1e30f;
            float l2 = (c2 < NC) ? g_logits[L + c2] + dsum[c2] : -1e30f;
            if (c1 < NC) g_logits[L + c1] = l1;
            if (c2 < NC) g_logits[L + c2] = l2;
            float m = fmaxf(l1, l2);
#pragma unroll
            for (int off = 16; off; off >>= 1) m = fmaxf(m, __shfl_xor_sync(0xffffffffu, m, off));
            float e1 = (c1 < NC) ? __expf(l1 - m) : 0.f;
            float e2 = (c2 < NC) ? __expf(l2 - m) : 0.f;
            float ss = e1 + e2;
#pragma unroll
            for (int off = 16; off; off >>= 1) ss += __shfl_xor_sync(0xffffffffu, ss, off);
            float inv = 1.f / ss;
            if (c1 < NC) probs[c1] = e1 * inv;
            if (c2 < NC) probs[c2] = e2 * inv;
        }
        __syncthreads();
        float p = probs[tid >> 2];
        acc.x = fmaf(p, pr.x, acc.x); acc.y = fmaf(p, pr.y, acc.y);
        acc.z = fmaf(p, pr.z, acc.z); acc.w = fmaf(p, pr.w, acc.w);
    }
    if (tid < CO4) {
        float* sp = &g_s[b * CO_TIMES_OD + tid * 4];
        atomicAdd(sp + 0, acc.x); atomicAdd(sp + 1, acc.y);
        atomicAdd(sp + 2, acc.z); atomicAdd(sp + 3, acc.w);
    }
}

// ---------------- final: scores = ||squash(s)|| = sn/(1+sn) ----------------
__global__ void k_final(float* __restrict__ out) {
    int idx = blockIdx.x * 256 + threadIdx.x;
    if (idx >= NB * NC) return;
    float sn = 0.f;
#pragma unroll
    for (int o = 0; o < 16; o++) { float v = g_s[idx * 16 + o]; sn = fmaf(v, v, sn); }
    out[idx] = sn / (1.f + sn);
}

// ---------------- launch ----------------
extern "C" void kernel_launch(void* const* d_in, const int* in_sizes, int n_in,
                              void* d_out, int out_size) {
    const float* x  = (const float*)d_in[0];
    const float* w1 = (const float*)d_in[1];
    const float* b1 = (const float*)d_in[2];
    const float* w2 = (const float*)d_in[3];
    const float* b2 = (const float*)d_in[4];
    const float* rw = (const float*)d_in[5];
    float* out = (float*)d_out;

    k_tr1p<<<270, 256>>>(w1);
    k_tr2p<<<8192, 256>>>(w2);
    k_conv1<<<dim3(24, 32), 256>>>(x, b1);
    k_prim<<<dim3(9, 32), 256>>>(b2);
    k_squash_u<<<(NB * NNODES + 255) / 256, 256>>>();
    k_priors<<<NNODES, 256>>>(rw);

    // iter 0: uniform probs (1/43 folded into squash scale)
    k_reduce0<<<64, 192>>>();
    k_squash_out<<<11, 256>>>(1.f / 43.f);

    // iter 1
    k_zero_logits<<<(NB * NNODES * NC + 255) / 256, 256>>>();
    k_zero_s<<<172, 256>>>();
    k_iter<<<dim3(81, NB), 256>>>();
    k_squash_out<<<11, 256>>>(1.f);

    // iter 2 (final)
    k_zero_s<<<172, 256>>>();
    k_iter<<<dim3(81, NB), 256>>>();
    k_final<<<11, 256>>>(out);
}

// round 4
// speedup vs baseline: 1.4638x; 1.4638x over previous
#include <cuda_runtime.h>
#include <cuda_fp16.h>
#include <math.h>

typedef unsigned long long ull;

// ---------------- problem constants ----------------
#define NB       64
#define NNODES   1296        // 16*81
#define NC       43
#define OD       16
#define CO_TIMES_OD 688      // 43*16
#define CO4      172         // 688/4

// packed f32x2 FMA (Blackwell sm_103a): two fp32 MACs per instruction, bit-exact fp32
#define FMA2(a,x,y) asm("fma.rn.f32x2 %0, %1, %2, %0;" : "+l"(a) : "l"(x), "l"(y))

static __device__ __forceinline__ float f2lo(ull v){ return __uint_as_float((unsigned)v); }
static __device__ __forceinline__ float f2hi(ull v){ return __uint_as_float((unsigned)(v>>32)); }
static __device__ __forceinline__ ull pack2(float w){ ull r; asm("mov.b64 %0, {%1, %1};" : "=l"(r) : "f"(w)); return r; }

// ---------------- device scratch ----------------
__device__ float  g_w1t[62208];                    // conv1 weights scalar: [(ci*9+ky)*9+kx][co]
__device__ float  g_w2t[2097152];                  // prim  weights scalar: [(g*8+ky)*8+kx][co]
__device__ float  g_h[NB * 256 * 24 * 24];         // conv1 output (relu'd)
__device__ float  g_u[NB * NNODES * 8];            // primary capsules (squashed in place)
__device__ ull    g_pri[(size_t)NB * NNODES * CO4];// priors, fp16x4 packed (114MB)
__device__ float  g_logits[NB * NNODES * NC];
__device__ float  g_s[NB * CO_TIMES_OD];
__device__ float  g_caps[NB * CO_TIMES_OD];

static __device__ __forceinline__ unsigned h2u(__half2 h){ return *reinterpret_cast<unsigned*>(&h); }
static __device__ __forceinline__ __half2 u2h(unsigned u){ return *reinterpret_cast<__half2*>(&u); }

static __device__ __forceinline__ float4 unpk(ull v) {
    float2 a = __half22float2(u2h((unsigned)v));
    float2 b = __half22float2(u2h((unsigned)(v >> 32)));
    return make_float4(a.x, a.y, b.x, b.y);
}

// ---------------- weight transposes (scalar, co-major for coalesced loads) ----------------
__global__ void k_tr1(const float* __restrict__ w) {
    int idx = blockIdx.x * 256 + threadIdx.x;
    if (idx >= 62208) return;
    int co = idx & 255; int r = idx >> 8;      // r = (ci*9+ky)*9+kx, 0..242
    int kx = r % 9; int t = r / 9; int ky = t % 9; int ci = t / 9;
    g_w1t[idx] = w[co * 243 + ci * 81 + ky * 9 + kx];
}
__global__ void k_tr2(const float* __restrict__ w) {
    int idx = blockIdx.x * 256 + threadIdx.x;   // 2,097,152 exact
    int co = idx & 127;
    int kx = (idx >> 7) & 7;
    int ky = (idx >> 10) & 7;
    int g  = idx >> 13;
    g_w2t[idx] = w[co * 16384 + g * 64 + ky * 8 + kx];
}

// ---------------- conv1: batch-paired f32x2, (64,3,32,32) -> (64,256,24,24) ----------------
__global__ __launch_bounds__(256, 2) void k_conv1(const float* __restrict__ x,
                                                  const float* __restrict__ bias) {
    int oy = blockIdx.x, bp = blockIdx.y;
    int b0 = bp, b1 = bp + 32;
    int co = threadIdx.x;
    __shared__ float2 xs[864];           // [3 ci][9 r][32 col], pair (b0,b1)
    for (int idx = co; idx < 864; idx += 256) {
        int ci = idx / 288, rem = idx - ci * 288;
        int r = rem >> 5, col = rem & 31;
        int off = (ci * 32 + oy + r) * 32 + col;
        xs[idx] = make_float2(x[b0 * 3072 + off], x[b1 * 3072 + off]);
    }
    __syncthreads();
    const ull* xsu = (const ull*)xs;
    float bv = bias[co];
#pragma unroll 1
    for (int h = 0; h < 2; h++) {        // two halves of the 24-wide output row
        ull acc[12];
#pragma unroll
        for (int i = 0; i < 12; i++) acc[i] = 0ull;
        for (int ci = 0; ci < 3; ci++) {
#pragma unroll
            for (int ky = 0; ky < 9; ky++) {
                ull in[20];
                const ulonglong2* ip = (const ulonglong2*)(xsu + ci * 288 + ky * 32 + h * 12);
#pragma unroll
                for (int j = 0; j < 10; j++) { ulonglong2 t = ip[j]; in[2*j] = t.x; in[2*j+1] = t.y; }
                const float* wp = &g_w1t[((ci * 9 + ky) * 9) * 256 + co];
                ull w[9];
#pragma unroll
                for (int kx = 0; kx < 9; kx++) w[kx] = pack2(wp[kx * 256]);
#pragma unroll
                for (int kx = 0; kx < 9; kx++)
#pragma unroll
                    for (int ox = 0; ox < 12; ox++)
                        FMA2(acc[ox], in[ox + kx], w[kx]);
            }
        }
        float* h0 = &g_h[((b0 * 256 + co) * 24 + oy) * 24 + h * 12];
        float* h1 = &g_h[((b1 * 256 + co) * 24 + oy) * 24 + h * 12];
#pragma unroll
        for (int ox = 0; ox < 12; ox++) {
            h0[ox] = fmaxf(f2lo(acc[ox]) + bv, 0.f);
            h1[ox] = fmaxf(f2hi(acc[ox]) + bv, 0.f);
        }
    }
}

// ---------------- prim conv: batch-paired f32x2, 8x8 s2 -> caps layout ----------------
__global__ __launch_bounds__(256, 2) void k_prim(const float* __restrict__ bias) {
    int oy = blockIdx.x, bp = blockIdx.y;
    int b0 = bp, b1 = bp + 32;
    int tid = threadIdx.x;
    int kh = tid >> 7;          // K-range half
    int co = tid & 127;
    __shared__ float2 hs[6144];   // 48KB: [32 ci][8 r][24 col], pair (b0,b1)
    const ull* hsu = (const ull*)hs;
    ull acc[9];
#pragma unroll
    for (int i = 0; i < 9; i++) acc[i] = 0ull;

    for (int cc = 0; cc < 8; cc++) {      // 8 chunks of 32 input channels
        __syncthreads();
        for (int idx = tid; idx < 6144; idx += 256) {
            int ci = idx / 192, rem = idx - ci * 192;
            int r = rem / 24, col = rem - r * 24;
            int off = ((cc * 32 + ci) * 24 + 2 * oy + r) * 24 + col;
            hs[idx] = make_float2(g_h[b0 * 147456 + off], g_h[b1 * 147456 + off]);
        }
        __syncthreads();
        for (int cil = kh * 16; cil < kh * 16 + 16; cil++) {
            int g = cc * 32 + cil;
#pragma unroll
            for (int ky = 0; ky < 8; ky++) {
                ull in[24];
                const ulonglong2* ip = (const ulonglong2*)(hsu + cil * 192 + ky * 24);
#pragma unroll
                for (int j = 0; j < 12; j++) { ulonglong2 t = ip[j]; in[2*j] = t.x; in[2*j+1] = t.y; }
                const float* wp = &g_w2t[((g * 8 + ky) * 8) * 128 + co];
                ull w[8];
#pragma unroll
                for (int kx = 0; kx < 8; kx++) w[kx] = pack2(wp[kx * 128]);
#pragma unroll
                for (int kx = 0; kx < 8; kx++)
#pragma unroll
                    for (int ox = 0; ox < 9; ox++)
                        FMA2(acc[ox], in[2 * ox + kx], w[kx]);
            }
        }
    }
    __syncthreads();
    ull* cm = (ull*)hs;
    if (kh == 1) {
#pragma unroll
        for (int ox = 0; ox < 9; ox++) cm[co * 9 + ox] = acc[ox];
    }
    __syncthreads();
    if (kh == 0) {
        float bv = bias[co];
        int i = co >> 4, g2 = co & 15;
#pragma unroll
        for (int ox = 0; ox < 9; ox++) {
            ull o = cm[co * 9 + ox];
            float v0 = f2lo(acc[ox]) + f2lo(o) + bv;
            float v1 = f2hi(acc[ox]) + f2hi(o) + bv;
            int n = g2 * 81 + oy * 9 + ox;
            g_u[(b0 * NNODES + n) * 8 + i] = v0;
            g_u[(b1 * NNODES + n) * 8 + i] = v1;
        }
    }
}

// ---------------- squash primary capsules (dim 8, in place) ----------------
__global__ void k_squash_u() {
    int node = blockIdx.x * 256 + threadIdx.x;
    if (node >= NB * NNODES) return;
    float v[8]; float sn = 0.f;
#pragma unroll
    for (int i = 0; i < 8; i++) { v[i] = g_u[node * 8 + i]; sn = fmaf(v[i], v[i], sn); }
    float f = sqrtf(sn) / (1.f + sn);
#pragma unroll
    for (int i = 0; i < 8; i++) g_u[node * 8 + i] = v[i] * f;
}

// ---------------- priors[b,n,c,o] = sum_i u[b,n,i] * W[n,c,i,o]; store fp16x4 ----------------
__global__ __launch_bounds__(256) void k_priors(const float* __restrict__ route_w) {
    int n = blockIdx.x, tid = threadIdx.x;
    __shared__ float rw[NC * 8 * OD];   // 5504
    __shared__ float us[NB * 8];        // 512
    for (int idx = tid; idx < 5504; idx += 256) rw[idx] = route_w[n * 5504 + idx];
    for (int idx = tid; idx < 512; idx += 256) {
        int b = idx >> 3, i = idx & 7;
        us[idx] = g_u[(b * NNODES + n) * 8 + i];
    }
    __syncthreads();
    if (tid < CO4) {
        int c = tid >> 2;
        int obase = (tid & 3) * 4;
        const float* rwc = &rw[c * 128 + obase];
        for (int b = 0; b < NB; b++) {
            const float* ub = &us[b * 8];
            float4 sum = make_float4(0.f, 0.f, 0.f, 0.f);
#pragma unroll
            for (int i = 0; i < 8; i++) {
                float u = ub[i];
                sum.x = fmaf(u, rwc[i * 16 + 0], sum.x);
                sum.y = fmaf(u, rwc[i * 16 + 1], sum.y);
                sum.z = fmaf(u, rwc[i * 16 + 2], sum.z);
                sum.w = fmaf(u, rwc[i * 16 + 3], sum.w);
            }
            __half2 p01 = __floats2half2_rn(sum.x, sum.y);
            __half2 p23 = __floats2half2_rn(sum.z, sum.w);
            ull v = (ull)h2u(p01) | ((ull)h2u(p23) << 32);
            g_pri[(size_t)(b * NNODES + n) * CO4 + tid] = v;
        }
    }
}

// ---------------- zero helpers ----------------
__global__ void k_zero_s() {
    int i = blockIdx.x * 256 + threadIdx.x;
    if (i < NB * CO_TIMES_OD) g_s[i] = 0.f;
}
__global__ void k_zero_logits() {
    int i = blockIdx.x * 256 + threadIdx.x;
    if (i < NB * NNODES * NC) g_logits[i] = 0.f;
}

// ---------------- iter0: s = sum_n priors (uniform probs folded into squash scale) ----------------
__global__ void k_reduce0() {
    int b = blockIdx.y, n0 = blockIdx.x * 81, tid = threadIdx.x;
    if (tid >= CO4) return;
    float4 acc = make_float4(0.f, 0.f, 0.f, 0.f);
    const ull* p = &g_pri[(size_t)(b * NNODES + n0) * CO4 + tid];
    for (int nn = 0; nn < 81; nn++) {
        float4 q = unpk(p[(size_t)nn * CO4]);
        acc.x += q.x; acc.y += q.y; acc.z += q.z; acc.w += q.w;
    }
    float* sp = &g_s[b * CO_TIMES_OD + tid * 4];
    atomicAdd(sp + 0, acc.x); atomicAdd(sp + 1, acc.y);
    atomicAdd(sp + 2, acc.z); atomicAdd(sp + 3, acc.w);
}

// ---------------- squash s -> output capsules ----------------
__global__ void k_squash_out(float scale) {
    int idx = blockIdx.x * 256 + threadIdx.x;
    if (idx >= NB * NC) return;
    float v[16]; float sn = 0.f;
#pragma unroll
    for (int o = 0; o < 16; o++) { v[o] = g_s[idx * 16 + o] * scale; sn = fmaf(v[o], v[o], sn); }
    float f = sqrtf(sn) / (1.f + sn);
#pragma unroll
    for (int o = 0; o < 16; o++) g_caps[idx * 16 + o] = v[o] * f;
}

// ---------------- routing iteration: delta -> logits -> softmax -> s accumulate ----------------
__global__ __launch_bounds__(256) void k_iter() {
    int b = blockIdx.y, n0 = blockIdx.x * 16, tid = threadIdx.x;
    __shared__ float dsum[48];
    __shared__ float probs[64];
    if (tid >= 43 && tid < 64) probs[tid] = 0.f;

    const float4* caps4 = reinterpret_cast<const float4*>(g_caps);
    float4 outs = make_float4(0.f, 0.f, 0.f, 0.f);
    if (tid < CO4) outs = caps4[b * CO4 + tid];
    float4 acc = make_float4(0.f, 0.f, 0.f, 0.f);

    for (int nn = 0; nn < 16; nn++) {
        int n = n0 + nn;
        float4 pr = make_float4(0.f, 0.f, 0.f, 0.f);
        if (tid < CO4) pr = unpk(g_pri[(size_t)(b * NNODES + n) * CO4 + tid]);
        // delta_c = sum_o priors * outputs  (4 lanes per class, reduce width 4)
        float t = pr.x * outs.x + pr.y * outs.y + pr.z * outs.z + pr.w * outs.w;
        t += __shfl_xor_sync(0xffffffffu, t, 2, 4);
        t += __shfl_xor_sync(0xffffffffu, t, 1, 4);
        if (tid < CO4 && (tid & 3) == 0) dsum[tid >> 2] = t;
        __syncthreads();
        if (tid < 32) {
            int c1 = tid, c2 = tid + 32;
            int L = (b * NNODES + n) * NC;
            float l1 = (c1 < NC) ? g_logits[L + c1] + dsum[c1] : -1e30f;
            float l2 = (c2 < NC) ? g_logits[L + c2] + dsum[c2] : -1e30f;
            if (c1 < NC) g_logits[L + c1] = l1;
            if (c2 < NC) g_logits[L + c2] = l2;
            float m = fmaxf(l1, l2);
#pragma unroll
            for (int off = 16; off; off >>= 1) m = fmaxf(m, __shfl_xor_sync(0xffffffffu, m, off));
            float e1 = (c1 < NC) ? __expf(l1 - m) : 0.f;
            float e2 = (c2 < NC) ? __expf(l2 - m) : 0.f;
            float ss = e1 + e2;
#pragma unroll
            for (int off = 16; off; off >>= 1) ss += __shfl_xor_sync(0xffffffffu, ss, off);
            float inv = 1.f / ss;
            if (c1 < NC) probs[c1] = e1 * inv;
            if (c2 < NC) probs[c2] = e2 * inv;
        }
        __syncthreads();
        float p = probs[tid >> 2];
        acc.x = fmaf(p, pr.x, acc.x); acc.y = fmaf(p, pr.y, acc.y);
        acc.z = fmaf(p, pr.z, acc.z); acc.w = fmaf(p, pr.w, acc.w);
    }
    if (tid < CO4) {
        float* sp = &g_s[b * CO_TIMES_OD + tid * 4];
        atomicAdd(sp + 0, acc.x); atomicAdd(sp + 1, acc.y);
        atomicAdd(sp + 2, acc.z); atomicAdd(sp + 3, acc.w);
    }
}

// ---------------- final: scores = ||squash(s)|| = sn/(1+sn) ----------------
__global__ void k_final(float* __restrict__ out) {
    int idx = blockIdx.x * 256 + threadIdx.x;
    if (idx >= NB * NC) return;
    float sn = 0.f;
#pragma unroll
    for (int o = 0; o < 16; o++) { float v = g_s[idx * 16 + o]; sn = fmaf(v, v, sn); }
    out[idx] = sn / (1.f + sn);
}

// ---------------- launch ----------------
extern "C" void kernel_launch(void* const* d_in, const int* in_sizes, int n_in,
                              void* d_out, int out_size) {
    const float* x  = (const float*)d_in[0];
    const float* w1 = (const float*)d_in[1];
    const float* b1 = (const float*)d_in[2];
    const float* w2 = (const float*)d_in[3];
    const float* b2 = (const float*)d_in[4];
    const float* rw = (const float*)d_in[5];
    float* out = (float*)d_out;

    k_tr1<<<243, 256>>>(w1);
    k_tr2<<<8192, 256>>>(w2);
    k_conv1<<<dim3(24, 32), 256>>>(x, b1);
    k_prim<<<dim3(9, 32), 256>>>(b2);
    k_squash_u<<<(NB * NNODES + 255) / 256, 256>>>();
    k_priors<<<NNODES, 256>>>(rw);

    // iter 0: uniform probs (1/43 folded into squash scale)
    k_zero_s<<<172, 256>>>();
    k_reduce0<<<dim3(16, NB), 192>>>();
    k_squash_out<<<11, 256>>>(1.f / 43.f);

    // iter 1
    k_zero_logits<<<(NB * NNODES * NC + 255) / 256, 256>>>();
    k_zero_s<<<172, 256>>>();
    k_iter<<<dim3(81, NB), 256>>>();
    k_squash_out<<<11, 256>>>(1.f);

    // iter 2 (final)
    k_zero_s<<<172, 256>>>();
    k_iter<<<dim3(81, NB), 256>>>();
    k_final<<<11, 256>>>(out);
}